// round 7
// baseline (speedup 1.0000x reference)
#include <cuda_runtime.h>
#include <cuda_bf16.h>
#include <math.h>
#include <stdint.h>

// TopKRouter: logits = x @ W^T (16384x4096 @ 4096x64), softmax, top-2, renorm.
// Split-bf16 (hi/lo) 3-product mma.sync.m16n8k16 GEMM, K-split x4 across warps.
// Round 7: 5 CTAs/SM register diet (<=96 regs) + streaming loads for x (__ldcs)
//          so L1 keeps B resident; streaming stores for logits.
// out fp32: [indices 16384*2][weights 16384*2][logits 16384*64]

#define TOKENS 16384
#define DIM    4096
#define NEXP   64
#define NKS    (DIM / 16)   // 256 k-steps total
#define KSW    (NKS / 4)    // 64 k-steps per warp

// Fragment-ordered pre-converted W, hi and lo interleaved:
// q = ((ks*8 + nt)*32 + lane): uint4 { hi(kb,kb+1), hi(kb+8,kb+9),
//                                      lo(kb,kb+1), lo(kb+8,kb+9) }
// with n = nt*8 + lane/4, kb = ks*16 + (lane%4)*2.
__device__ uint4 g_B[NKS * 8 * 32];

__device__ __forceinline__ void split2(float a, float b, unsigned& h, unsigned& l) {
    asm("cvt.rn.bf16x2.f32 %0, %1, %2;" : "=r"(h) : "f"(b), "f"(a));
    float ha = __uint_as_float(h << 16);
    float hb = __uint_as_float(h & 0xFFFF0000u);
    float ra = a - ha;
    float rb = b - hb;
    asm("cvt.rn.bf16x2.f32 %0, %1, %2;" : "=r"(l) : "f"(rb), "f"(ra));
}

__device__ __forceinline__ void mma16816(float* c, unsigned a0, unsigned a1,
                                         unsigned a2, unsigned a3,
                                         unsigned b0, unsigned b1) {
    asm volatile(
        "mma.sync.aligned.m16n8k16.row.col.f32.bf16.bf16.f32 "
        "{%0,%1,%2,%3}, {%4,%5,%6,%7}, {%8,%9}, {%0,%1,%2,%3};"
        : "+f"(c[0]), "+f"(c[1]), "+f"(c[2]), "+f"(c[3])
        : "r"(a0), "r"(a1), "r"(a2), "r"(a3), "r"(b0), "r"(b1));
}

// ---------------- W pre-convert (fragment order, interleaved) ----------------
__global__ void convert_w_kernel(const float* __restrict__ Wg) {
    int q = blockIdx.x * blockDim.x + threadIdx.x;   // 0..65535
    int ks   = q >> 8;
    int nt   = (q >> 5) & 7;
    int lane = q & 31;
    int n  = nt * 8 + (lane >> 2);
    int kb = ks * 16 + (lane & 3) * 2;
    const float* wr = Wg + (size_t)n * DIM + kb;
    unsigned hx, lx, hy, ly;
    split2(wr[0], wr[1], hx, lx);
    split2(wr[8], wr[9], hy, ly);
    g_B[q] = make_uint4(hx, hy, lx, ly);
}

__device__ __forceinline__ bool better(float v, int i, float v2, int i2) {
    return (v > v2) || (v == v2 && i < i2);
}

// ---------------- main kernel ----------------
// CTA: 4 warps, same 16 tokens, K quarters. Partial-acc reduce through smem.
__global__ __launch_bounds__(128, 5) void router_kernel(
    const float* __restrict__ x,
    float* __restrict__ out)
{
    __shared__ float red[3 * 32 * 33];   // 3 partials x 32 lanes x 32 floats, pad 33

    const int tid  = threadIdx.x;
    const int wid  = tid >> 5;           // K quarter 0..3
    const int lane = tid & 31;
    const int r0   = blockIdx.x * 16 + (lane >> 2);   // rows r0, r0+8
    const int kbase = wid * KSW;

    const float2* pA0 = (const float2*)(x + (size_t)r0 * DIM) + (lane & 3);
    const float2* pA1 = pA0 + 4 * DIM;   // row r0+8

    float acc[8][4];
    #pragma unroll
    for (int nt = 0; nt < 8; nt++)
        #pragma unroll
        for (int j = 0; j < 4; j++) acc[nt][j] = 0.0f;

    const uint4* __restrict__ B = g_B + lane;

    #pragma unroll 2
    for (int s = 0; s < KSW; s++) {
        const int ks = kbase + s;
        // x is strictly streaming: evict-first so B stays in L1
        float2 v00 = __ldcs(pA0 + ks * 8);
        float2 v01 = __ldcs(pA0 + ks * 8 + 4);
        float2 v10 = __ldcs(pA1 + ks * 8);
        float2 v11 = __ldcs(pA1 + ks * 8 + 4);

        unsigned ah0, ah1, ah2, ah3, al0, al1, al2, al3;
        split2(v00.x, v00.y, ah0, al0);
        split2(v10.x, v10.y, ah1, al1);
        split2(v01.x, v01.y, ah2, al2);
        split2(v11.x, v11.y, ah3, al3);

        const uint4* b = B + ks * 256;
        #pragma unroll
        for (int nt = 0; nt < 8; nt++) {
            uint4 bv = __ldg(b + nt * 32);
            mma16816(acc[nt], ah0, ah1, ah2, ah3, bv.x, bv.y);   // hi * hi
            mma16816(acc[nt], ah0, ah1, ah2, ah3, bv.z, bv.w);   // hi * lo
            mma16816(acc[nt], al0, al1, al2, al3, bv.x, bv.y);   // lo * hi
        }
    }

    // ---- cross-warp K reduction via smem ----
    if (wid != 0) {
        float* dst = red + ((wid - 1) * 32 + lane) * 33;
        #pragma unroll
        for (int nt = 0; nt < 8; nt++)
            #pragma unroll
            for (int j = 0; j < 4; j++)
                dst[nt * 4 + j] = acc[nt][j];
    }
    __syncthreads();
    if (wid != 0) return;

    #pragma unroll
    for (int p = 0; p < 3; p++) {
        const float* src = red + (p * 32 + lane) * 33;
        #pragma unroll
        for (int nt = 0; nt < 8; nt++)
            #pragma unroll
            for (int j = 0; j < 4; j++)
                acc[nt][j] += src[nt * 4 + j];
    }

    // ---- write logits (streaming stores) ----
    float* lg = out + 4 * TOKENS;
    const int cbase = (lane & 3) * 2;
    #pragma unroll
    for (int nt = 0; nt < 8; nt++) {
        int c = nt * 8 + cbase;
        __stcs((float2*)(lg + (size_t)r0 * NEXP + c),       make_float2(acc[nt][0], acc[nt][1]));
        __stcs((float2*)(lg + (size_t)(r0 + 8) * NEXP + c), make_float2(acc[nt][2], acc[nt][3]));
    }

    // ---- per-row top-2 (register scan + quad shuffle merge) ----
    #pragma unroll
    for (int half = 0; half < 2; half++) {
        const int row = r0 + half * 8;
        float m1 = -INFINITY, m2 = -INFINITY;
        int i1 = 0, i2 = 0;
        #pragma unroll
        for (int nt = 0; nt < 8; nt++) {
            #pragma unroll
            for (int j = 0; j < 2; j++) {
                float v = acc[nt][half * 2 + j];
                int e = nt * 8 + cbase + j;
                if (v > m1)      { m2 = m1; i2 = i1; m1 = v; i1 = e; }
                else if (v > m2) { m2 = v; i2 = e; }
            }
        }
        #pragma unroll
        for (int d = 1; d < 4; d <<= 1) {
            float om1 = __shfl_xor_sync(0xFFFFFFFF, m1, d);
            int   oi1 = __shfl_xor_sync(0xFFFFFFFF, i1, d);
            float om2 = __shfl_xor_sync(0xFFFFFFFF, m2, d);
            int   oi2 = __shfl_xor_sync(0xFFFFFFFF, i2, d);
            if (better(om1, oi1, m1, i1)) {
                float nm2; int ni2;
                if (better(m1, i1, om2, oi2)) { nm2 = m1; ni2 = i1; }
                else                          { nm2 = om2; ni2 = oi2; }
                m1 = om1; i1 = oi1; m2 = nm2; i2 = ni2;
            } else {
                if (better(om1, oi1, m2, i2)) { m2 = om1; i2 = oi1; }
            }
        }
        if ((lane & 3) == 0) {
            // top-2 renorm of full softmax == logistic of (m1 - m2); +1e-9 negligible
            float e2 = __expf(m2 - m1);
            float rcp = 1.0f / (1.0f + e2);
            out[(size_t)row * 2 + 0] = (float)i1;
            out[(size_t)row * 2 + 1] = (float)i2;
            out[2 * TOKENS + (size_t)row * 2 + 0] = rcp;
            out[2 * TOKENS + (size_t)row * 2 + 1] = e2 * rcp;
        }
    }
}

extern "C" void kernel_launch(void* const* d_in, const int* in_sizes, int n_in,
                              void* d_out, int out_size)
{
    const float* x  = (const float*)d_in[0];
    const float* Wg = (const float*)d_in[1];
    float* out = (float*)d_out;

    convert_w_kernel<<<256, 256>>>(Wg);
    router_kernel<<<TOKENS / 16, 128>>>(x, out);
}

// round 8
// speedup vs baseline: 1.0676x; 1.0676x over previous
#include <cuda_runtime.h>
#include <cuda_bf16.h>
#include <math.h>
#include <stdint.h>

// TopKRouter: logits = x @ W^T (16384x4096 @ 4096x64), softmax, top-2, renorm.
// Split-bf16 (hi/lo) 3-product mma.sync.m16n8k16 GEMM, K-split x4 across warps.
// Round 8: 32 tokens/warp (two m16 tiles share each B fragment) -> B traffic
//          halves, MMA/issue-slot ratio up. Proven 128-reg/4-CTA envelope.
// out fp32: [indices 16384*2][weights 16384*2][logits 16384*64]

#define TOKENS 16384
#define DIM    4096
#define NEXP   64
#define NKS    (DIM / 16)   // 256 k-steps total
#define KSW    (NKS / 4)    // 64 k-steps per warp

// Fragment-ordered pre-converted W, hi and lo interleaved:
// q = ((ks*8 + nt)*32 + lane): uint4 { hi(kb,kb+1), hi(kb+8,kb+9),
//                                      lo(kb,kb+1), lo(kb+8,kb+9) }
// with n = nt*8 + lane/4, kb = ks*16 + (lane%4)*2.
__device__ uint4 g_B[NKS * 8 * 32];

__device__ __forceinline__ void split2(float a, float b, unsigned& h, unsigned& l) {
    asm("cvt.rn.bf16x2.f32 %0, %1, %2;" : "=r"(h) : "f"(b), "f"(a));
    float ha = __uint_as_float(h << 16);
    float hb = __uint_as_float(h & 0xFFFF0000u);
    float ra = a - ha;
    float rb = b - hb;
    asm("cvt.rn.bf16x2.f32 %0, %1, %2;" : "=r"(l) : "f"(rb), "f"(ra));
}

__device__ __forceinline__ void mma16816(float* c, unsigned a0, unsigned a1,
                                         unsigned a2, unsigned a3,
                                         unsigned b0, unsigned b1) {
    asm volatile(
        "mma.sync.aligned.m16n8k16.row.col.f32.bf16.bf16.f32 "
        "{%0,%1,%2,%3}, {%4,%5,%6,%7}, {%8,%9}, {%0,%1,%2,%3};"
        : "+f"(c[0]), "+f"(c[1]), "+f"(c[2]), "+f"(c[3])
        : "r"(a0), "r"(a1), "r"(a2), "r"(a3), "r"(b0), "r"(b1));
}

// ---------------- W pre-convert (fragment order, interleaved) ----------------
__global__ void convert_w_kernel(const float* __restrict__ Wg) {
    int q = blockIdx.x * blockDim.x + threadIdx.x;   // 0..65535
    int ks   = q >> 8;
    int nt   = (q >> 5) & 7;
    int lane = q & 31;
    int n  = nt * 8 + (lane >> 2);
    int kb = ks * 16 + (lane & 3) * 2;
    const float* wr = Wg + (size_t)n * DIM + kb;
    unsigned hx, lx, hy, ly;
    split2(wr[0], wr[1], hx, lx);
    split2(wr[8], wr[9], hy, ly);
    g_B[q] = make_uint4(hx, hy, lx, ly);
}

__device__ __forceinline__ bool better(float v, int i, float v2, int i2) {
    return (v > v2) || (v == v2 && i < i2);
}

// ---------------- main kernel ----------------
// CTA: 4 warps, same 32 tokens, K quarters. Partial-acc reduce through smem.
__global__ __launch_bounds__(128, 4) void router_kernel(
    const float* __restrict__ x,
    float* __restrict__ out)
{
    __shared__ float red[3 * 32 * 65];   // 3 partials x 32 lanes x 64 floats, pad 65

    const int tid  = threadIdx.x;
    const int wid  = tid >> 5;           // K quarter 0..3
    const int lane = tid & 31;
    const int r0   = blockIdx.x * 32 + (lane >> 2);   // rows r0, +8, +16, +24
    const int kbase = wid * KSW;

    const float2* pA0 = (const float2*)(x + (size_t)r0 * DIM) + (lane & 3);
    const float2* pA1 = pA0 + 4 * DIM;    // +8 rows
    const float2* pA2 = pA0 + 8 * DIM;    // +16 rows
    const float2* pA3 = pA0 + 12 * DIM;   // +24 rows

    float acc0[8][4], acc1[8][4];
    #pragma unroll
    for (int nt = 0; nt < 8; nt++)
        #pragma unroll
        for (int j = 0; j < 4; j++) { acc0[nt][j] = 0.0f; acc1[nt][j] = 0.0f; }

    const uint4* __restrict__ B = g_B + lane;

    #pragma unroll 2
    for (int s = 0; s < KSW; s++) {
        const int ks = kbase + s;
        float2 v00 = __ldg(pA0 + ks * 8);
        float2 v01 = __ldg(pA0 + ks * 8 + 4);
        float2 v10 = __ldg(pA1 + ks * 8);
        float2 v11 = __ldg(pA1 + ks * 8 + 4);
        float2 v20 = __ldg(pA2 + ks * 8);
        float2 v21 = __ldg(pA2 + ks * 8 + 4);
        float2 v30 = __ldg(pA3 + ks * 8);
        float2 v31 = __ldg(pA3 + ks * 8 + 4);

        // tile0: rows r0, r0+8 ; tile1: rows r0+16, r0+24
        unsigned ah0, ah1, ah2, ah3, al0, al1, al2, al3;
        unsigned ch0, ch1, ch2, ch3, cl0, cl1, cl2, cl3;
        split2(v00.x, v00.y, ah0, al0);
        split2(v10.x, v10.y, ah1, al1);
        split2(v01.x, v01.y, ah2, al2);
        split2(v11.x, v11.y, ah3, al3);
        split2(v20.x, v20.y, ch0, cl0);
        split2(v30.x, v30.y, ch1, cl1);
        split2(v21.x, v21.y, ch2, cl2);
        split2(v31.x, v31.y, ch3, cl3);

        const uint4* b = B + ks * 256;
        #pragma unroll
        for (int nt = 0; nt < 8; nt++) {
            uint4 bv = __ldg(b + nt * 32);
            mma16816(acc0[nt], ah0, ah1, ah2, ah3, bv.x, bv.y);   // hi*hi
            mma16816(acc0[nt], ah0, ah1, ah2, ah3, bv.z, bv.w);   // hi*lo
            mma16816(acc0[nt], al0, al1, al2, al3, bv.x, bv.y);   // lo*hi
            mma16816(acc1[nt], ch0, ch1, ch2, ch3, bv.x, bv.y);
            mma16816(acc1[nt], ch0, ch1, ch2, ch3, bv.z, bv.w);
            mma16816(acc1[nt], cl0, cl1, cl2, cl3, bv.x, bv.y);
        }
    }

    // ---- cross-warp K reduction via smem ----
    if (wid != 0) {
        float* dst = red + ((wid - 1) * 32 + lane) * 65;
        #pragma unroll
        for (int nt = 0; nt < 8; nt++)
            #pragma unroll
            for (int j = 0; j < 4; j++) {
                dst[nt * 4 + j]      = acc0[nt][j];
                dst[32 + nt * 4 + j] = acc1[nt][j];
            }
    }
    __syncthreads();
    if (wid != 0) return;

    #pragma unroll
    for (int p = 0; p < 3; p++) {
        const float* src = red + (p * 32 + lane) * 65;
        #pragma unroll
        for (int nt = 0; nt < 8; nt++)
            #pragma unroll
            for (int j = 0; j < 4; j++) {
                acc0[nt][j] += src[nt * 4 + j];
                acc1[nt][j] += src[32 + nt * 4 + j];
            }
    }

    // ---- write logits ----
    float* lg = out + 4 * TOKENS;
    const int cbase = (lane & 3) * 2;
    #pragma unroll
    for (int nt = 0; nt < 8; nt++) {
        int c = nt * 8 + cbase;
        *(float2*)(lg + (size_t)r0 * NEXP + c)        = make_float2(acc0[nt][0], acc0[nt][1]);
        *(float2*)(lg + (size_t)(r0 + 8) * NEXP + c)  = make_float2(acc0[nt][2], acc0[nt][3]);
        *(float2*)(lg + (size_t)(r0 + 16) * NEXP + c) = make_float2(acc1[nt][0], acc1[nt][1]);
        *(float2*)(lg + (size_t)(r0 + 24) * NEXP + c) = make_float2(acc1[nt][2], acc1[nt][3]);
    }

    // ---- per-row top-2 (register scan + quad shuffle merge), 4 rows ----
    #pragma unroll
    for (int q = 0; q < 4; q++) {
        const int row = r0 + q * 8;
        float (*ac)[4] = (q < 2) ? acc0 : acc1;
        const int half = q & 1;
        float m1 = -INFINITY, m2 = -INFINITY;
        int i1 = 0, i2 = 0;
        #pragma unroll
        for (int nt = 0; nt < 8; nt++) {
            #pragma unroll
            for (int j = 0; j < 2; j++) {
                float v = ac[nt][half * 2 + j];
                int e = nt * 8 + cbase + j;
                if (v > m1)      { m2 = m1; i2 = i1; m1 = v; i1 = e; }
                else if (v > m2) { m2 = v; i2 = e; }
            }
        }
        #pragma unroll
        for (int d = 1; d < 4; d <<= 1) {
            float om1 = __shfl_xor_sync(0xFFFFFFFF, m1, d);
            int   oi1 = __shfl_xor_sync(0xFFFFFFFF, i1, d);
            float om2 = __shfl_xor_sync(0xFFFFFFFF, m2, d);
            int   oi2 = __shfl_xor_sync(0xFFFFFFFF, i2, d);
            if (better(om1, oi1, m1, i1)) {
                float nm2; int ni2;
                if (better(m1, i1, om2, oi2)) { nm2 = m1; ni2 = i1; }
                else                          { nm2 = om2; ni2 = oi2; }
                m1 = om1; i1 = oi1; m2 = nm2; i2 = ni2;
            } else {
                if (better(om1, oi1, m2, i2)) { m2 = om1; i2 = oi1; }
            }
        }
        if ((lane & 3) == 0) {
            // top-2 renorm of full softmax == logistic of (m1 - m2); +1e-9 negligible
            float e2 = __expf(m2 - m1);
            float rcp = 1.0f / (1.0f + e2);
            out[(size_t)row * 2 + 0] = (float)i1;
            out[(size_t)row * 2 + 1] = (float)i2;
            out[2 * TOKENS + (size_t)row * 2 + 0] = rcp;
            out[2 * TOKENS + (size_t)row * 2 + 1] = e2 * rcp;
        }
    }
}

extern "C" void kernel_launch(void* const* d_in, const int* in_sizes, int n_in,
                              void* d_out, int out_size)
{
    const float* x  = (const float*)d_in[0];
    const float* Wg = (const float*)d_in[1];
    float* out = (float*)d_out;

    convert_w_kernel<<<256, 256>>>(Wg);
    router_kernel<<<TOKENS / 32, 128>>>(x, out);
}